// round 1
// baseline (speedup 1.0000x reference)
#include <cuda_runtime.h>

#define BT_TOK 32768      // B*T = 16*2048
#define IN_DIM 768
#define ENC 512
#define CDIM 128
#define NCB 8
#define CBS 1024
#define LOSS_BLOCKS 4096  // BT_TOK / 8 tokens-per-block

// ---------------- scratch (static device globals; no allocations) ----------
__device__ float g_R[BT_TOK * ENC];                    // residual (64MB)
__device__ float g_Ze[BT_TOK * CDIM];                  // z_e      (16MB)
__device__ unsigned long long g_packed[BT_TOK];        // (distkey<<32)|idx
__device__ float g_cbnorm[NCB * CBS];                  // ||c||^2
__device__ float g_lossPartial[NCB * LOSS_BLOCKS];     // deterministic partials

// ---------------- generic SGEMM: 128x128 tile, BK=8, 256 threads, 8x8/thread
// C[M x N] = A[M x K] @ B[K x N]   (+bias | -=acc | A gathered via packed idx)
template<bool BIAS, bool GATHER, bool SUB>
__global__ __launch_bounds__(256) void sgemm(
    const float* __restrict__ A, const float* __restrict__ B,
    float* __restrict__ C, const float* __restrict__ bias,
    const unsigned long long* __restrict__ packed,
    const float* __restrict__ gtab, int K, int N)
{
    __shared__ float As[8][128];
    __shared__ float Bs[8][128];
    const int tid = threadIdx.x;
    const int tx = tid & 15, ty = tid >> 4;
    const int m0 = blockIdx.x * 128;
    const int n0 = blockIdx.y * 128;
    const int lr = tid >> 1;          // 0..127 : A-tile row
    const int lk = (tid & 1) * 4;     // 0 or 4 : A-tile k offset
    const int bk = tid >> 5;          // 0..7   : B-tile k row
    const int bn = (tid & 31) * 4;    // B-tile n offset

    const float* arow;
    if (GATHER) {
        unsigned idx = (unsigned)(packed[m0 + lr] & 0xffffffffu);
        arow = gtab + (size_t)idx * CDIM;
    } else {
        arow = A + (size_t)(m0 + lr) * K;
    }

    float acc[8][8];
#pragma unroll
    for (int i = 0; i < 8; ++i)
#pragma unroll
        for (int j = 0; j < 8; ++j) acc[i][j] = 0.f;

    for (int k0 = 0; k0 < K; k0 += 8) {
        float4 av = *(const float4*)(arow + k0 + lk);
        As[lk + 0][lr] = av.x; As[lk + 1][lr] = av.y;
        As[lk + 2][lr] = av.z; As[lk + 3][lr] = av.w;
        float4 bv = *(const float4*)(B + (size_t)(k0 + bk) * N + n0 + bn);
        *(float4*)&Bs[bk][bn] = bv;
        __syncthreads();
#pragma unroll
        for (int k = 0; k < 8; ++k) {
            float a[8], b[8];
            *(float4*)(a)     = *(const float4*)&As[k][ty * 8];
            *(float4*)(a + 4) = *(const float4*)&As[k][ty * 8 + 4];
            *(float4*)(b)     = *(const float4*)&Bs[k][tx * 8];
            *(float4*)(b + 4) = *(const float4*)&Bs[k][tx * 8 + 4];
#pragma unroll
            for (int i = 0; i < 8; ++i)
#pragma unroll
                for (int j = 0; j < 8; ++j)
                    acc[i][j] += a[i] * b[j];
        }
        __syncthreads();
    }

#pragma unroll
    for (int i = 0; i < 8; ++i) {
        int m = m0 + ty * 8 + i;
        float* crow = C + (size_t)m * N + n0 + tx * 8;
        if (SUB) {
#pragma unroll
            for (int j = 0; j < 8; ++j) crow[j] -= acc[i][j];
        } else if (BIAS) {
#pragma unroll
            for (int j = 0; j < 8; ++j) crow[j] = acc[i][j] + bias[n0 + tx * 8 + j];
        } else {
#pragma unroll
            for (int j = 0; j < 8; ++j) crow[j] = acc[i][j];
        }
    }
}

// ---------------- distance + argmin kernel --------------------------------
// acc = Ze[m] . cb[n]; d' = ||cb[n]||^2 - 2*acc  (||ze||^2 dropped: argmin-equiv)
// key = monotonic-float(d')<<32 | n ; atomicMin -> exact first-min tie behavior
__global__ __launch_bounds__(256) void dist_kernel(
    const float* __restrict__ Ze, const float* __restrict__ cb,
    const float* __restrict__ cbn, unsigned long long* __restrict__ packed)
{
    __shared__ float As[8][128];
    __shared__ float Bs[8][128];
    const int tid = threadIdx.x;
    const int tx = tid & 15, ty = tid >> 4;
    const int m0 = blockIdx.x * 128;
    const int n0 = blockIdx.y * 128;
    const int lr = tid >> 1;
    const int lk = (tid & 1) * 4;

    const float* arow = Ze + (size_t)(m0 + lr) * CDIM;
    const float* brow = cb + (size_t)(n0 + lr) * CDIM;   // transposed load

    float acc[8][8];
#pragma unroll
    for (int i = 0; i < 8; ++i)
#pragma unroll
        for (int j = 0; j < 8; ++j) acc[i][j] = 0.f;

    for (int k0 = 0; k0 < CDIM; k0 += 8) {
        float4 av = *(const float4*)(arow + k0 + lk);
        As[lk + 0][lr] = av.x; As[lk + 1][lr] = av.y;
        As[lk + 2][lr] = av.z; As[lk + 3][lr] = av.w;
        float4 bv = *(const float4*)(brow + k0 + lk);
        Bs[lk + 0][lr] = bv.x; Bs[lk + 1][lr] = bv.y;
        Bs[lk + 2][lr] = bv.z; Bs[lk + 3][lr] = bv.w;
        __syncthreads();
#pragma unroll
        for (int k = 0; k < 8; ++k) {
            float a[8], b[8];
            *(float4*)(a)     = *(const float4*)&As[k][ty * 8];
            *(float4*)(a + 4) = *(const float4*)&As[k][ty * 8 + 4];
            *(float4*)(b)     = *(const float4*)&Bs[k][tx * 8];
            *(float4*)(b + 4) = *(const float4*)&Bs[k][tx * 8 + 4];
#pragma unroll
            for (int i = 0; i < 8; ++i)
#pragma unroll
                for (int j = 0; j < 8; ++j)
                    acc[i][j] += a[i] * b[j];
        }
        __syncthreads();
    }

#pragma unroll
    for (int i = 0; i < 8; ++i) {
        unsigned long long best = ~0ull;
#pragma unroll
        for (int j = 0; j < 8; ++j) {
            int n = n0 + tx * 8 + j;
            float d = cbn[n] - 2.0f * acc[i][j];
            unsigned ib = __float_as_uint(d);
            ib ^= (ib & 0x80000000u) ? 0xffffffffu : 0x80000000u; // monotonic map
            unsigned long long key = ((unsigned long long)ib << 32) | (unsigned)n;
            if (key < best) best = key;
        }
        // reduce across the 16 lanes that share this row (tx dimension)
#pragma unroll
        for (int off = 8; off >= 1; off >>= 1) {
            unsigned long long o = __shfl_xor_sync(0xffffffffu, best, off);
            if (o < best) best = o;
        }
        if (tx == 0) atomicMin(&packed[m0 + ty * 8 + i], best);
    }
}

// ---------------- helpers ---------------------------------------------------
__global__ void init_packed_kernel()
{
    int i = blockIdx.x * blockDim.x + threadIdx.x;
    if (i < BT_TOK) g_packed[i] = ~0ull;
}

// one warp per row: deterministic fixed-order reduction of ||row||^2
__global__ void norm_kernel(const float* __restrict__ cb, float* __restrict__ out, int rows)
{
    int w = (blockIdx.x * blockDim.x + threadIdx.x) >> 5;
    int lane = threadIdx.x & 31;
    if (w >= rows) return;
    const float* r = cb + (size_t)w * CDIM;
    float s = 0.f;
#pragma unroll
    for (int q = 0; q < 4; ++q) { float v = r[lane + q * 32]; s += v * v; }
#pragma unroll
    for (int off = 16; off >= 1; off >>= 1) s += __shfl_xor_sync(0xffffffffu, s, off);
    if (lane == 0) out[w] = s;
}

// per-token: write code (as float) + accumulate (z_e - z_q)^2, deterministic
__global__ __launch_bounds__(256) void loss_kernel(
    const float* __restrict__ Ze, const float* __restrict__ cb,
    const unsigned long long* __restrict__ packed,
    float* __restrict__ out_codes, int stage, float* __restrict__ partial)
{
    __shared__ float ws[8];
    int wid = threadIdx.x >> 5, lane = threadIdx.x & 31;
    int t = blockIdx.x * 8 + wid;
    unsigned idx = (unsigned)(packed[t] & 0xffffffffu);
    const float* ze = Ze + (size_t)t * CDIM;
    const float* zq = cb + (size_t)idx * CDIM;
    float s = 0.f;
#pragma unroll
    for (int q = 0; q < 4; ++q) {
        float d = ze[lane + q * 32] - zq[lane + q * 32];
        s += d * d;
    }
#pragma unroll
    for (int off = 16; off >= 1; off >>= 1) s += __shfl_xor_sync(0xffffffffu, s, off);
    if (lane == 0) {
        ws[wid] = s;
        out_codes[(size_t)t * NCB + stage] = (float)idx;
    }
    __syncthreads();
    if (threadIdx.x == 0) {
        float tot = 0.f;
        for (int w = 0; w < 8; ++w) tot += ws[w];
        partial[blockIdx.x] = tot;
    }
}

// fixed-tree final reduction -> out[BT_TOK*NCB] = total vq loss
__global__ void final_loss_kernel(const float* __restrict__ partial, float* __restrict__ out)
{
    __shared__ float s[256];
    float v = 0.f;
    const int per = (NCB * LOSS_BLOCKS) / 256;   // 128
    for (int q = 0; q < per; ++q) v += partial[threadIdx.x * per + q];
    s[threadIdx.x] = v;
    __syncthreads();
    for (int st = 128; st > 0; st >>= 1) {
        if (threadIdx.x < st) s[threadIdx.x] += s[threadIdx.x + st];
        __syncthreads();
    }
    if (threadIdx.x == 0)
        out[(size_t)BT_TOK * NCB] = 1.25f * s[0] / (float)((size_t)BT_TOK * CDIM);
}

// ---------------- launch ----------------------------------------------------
extern "C" void kernel_launch(void* const* d_in, const int* in_sizes, int n_in,
                              void* d_out, int out_size)
{
    const float* z    = (const float*)d_in[0];   // (16,2048,768)
    const float* Win  = (const float*)d_in[1];   // (768,512)
    const float* bin  = (const float*)d_in[2];   // (512,)
    const float* cbs  = (const float*)d_in[3];   // (8,1024,128)
    const float* inw  = (const float*)d_in[4];   // (8,512,128)
    const float* outw = (const float*)d_in[5];   // (8,128,512)
    float* out = (float*)d_out;

    float *gR, *gZe, *gCbn, *gLP;
    unsigned long long* gPk;
    cudaGetSymbolAddress((void**)&gR,  g_R);
    cudaGetSymbolAddress((void**)&gZe, g_Ze);
    cudaGetSymbolAddress((void**)&gCbn, g_cbnorm);
    cudaGetSymbolAddress((void**)&gLP, g_lossPartial);
    cudaGetSymbolAddress((void**)&gPk, g_packed);

    // 1. residual = z @ W_in + b_in
    sgemm<true, false, false><<<dim3(BT_TOK / 128, ENC / 128), 256>>>(
        z, Win, gR, bin, nullptr, nullptr, IN_DIM, ENC);

    // 2. codebook norms (all stages at once)
    norm_kernel<<<(NCB * CBS * 32) / 256, 256>>>(cbs, gCbn, NCB * CBS);

    for (int i = 0; i < NCB; ++i) {
        const float* cb_i = cbs + (size_t)i * CBS * CDIM;

        init_packed_kernel<<<BT_TOK / 256, 256>>>();

        // z_e = R @ in_w[i]
        sgemm<false, false, false><<<dim3(BT_TOK / 128, CDIM / 128), 256>>>(
            gR, inw + (size_t)i * ENC * CDIM, gZe, nullptr, nullptr, nullptr, ENC, CDIM);

        // distances + argmin
        dist_kernel<<<dim3(BT_TOK / 128, CBS / 128), 256>>>(
            gZe, cb_i, gCbn + i * CBS, gPk);

        // codes + loss partials
        loss_kernel<<<LOSS_BLOCKS, 256>>>(gZe, cb_i, gPk, out, i, gLP + i * LOSS_BLOCKS);

        // R -= cb[idx] @ out_w[i]   (gathered A)
        sgemm<false, true, true><<<dim3(BT_TOK / 128, ENC / 128), 256>>>(
            nullptr, outw + (size_t)i * CDIM * ENC, gR, nullptr, gPk, cb_i, CDIM, ENC);
    }

    final_loss_kernel<<<1, 256>>>(gLP, out);
}